// round 2
// baseline (speedup 1.0000x reference)
#include <cuda_runtime.h>
#include <cuda_bf16.h>
#include <cstdint>

// ---------------------------------------------------------------------------
// OnlyLinear chain: y = x@W0^T+b0 -> ... -> @W8^T+b8  (no activations)
// Collapse to y = x @ Mf + cf with Mf = A0*A1*...*A8 (Ai = Wi^T), then one
// memory/FMA-balanced fused GEMV pass.
// ---------------------------------------------------------------------------

#define BATCH      65536
#define D_IN       784
#define D1         69
#define D2         31
#define D_OUT      10
#define M_PITCH    11          // shared pitch for Mf (coprime with 32 -> conflict-free)

// __device__ scratch (allocation-free rule: static device arrays)
__device__ float g_T1[D_IN * D2];       // 784 x 31
__device__ float g_c1[D2];
__device__ float g_T2[D_IN * D_OUT];    // 784 x 10
__device__ float g_c2[D_OUT];
__device__ float g_Mf[D_IN * D_OUT];    // final collapsed matrix
__device__ float g_cf[D_OUT];           // final collapsed bias

// ---- Stage 1: T1 = A0 @ A1  (784x69 * 69x31), c1 = b0@A1 + b1 --------------
__global__ void collapse1(const float* __restrict__ W0, const float* __restrict__ b0,
                          const float* __restrict__ W1, const float* __restrict__ b1) {
    int e = blockIdx.x * blockDim.x + threadIdx.x;
    if (e < D_IN * D2) {
        int i = e % D_IN;          // consecutive threads -> consecutive i -> coalesced W0 reads
        int j = e / D_IN;
        float s = 0.f;
        #pragma unroll 4
        for (int k = 0; k < D1; ++k)
            s = fmaf(W0[k * D_IN + i], W1[j * D1 + k], s);
        g_T1[i * D2 + j] = s;
    }
    if (e < D2) {
        float s = 0.f;
        for (int k = 0; k < D1; ++k)
            s = fmaf(b0[k], W1[e * D1 + k], s);
        g_c1[e] = s + b1[e];
    }
}

// ---- Stage 2: T2 = T1 @ A2 (784x31 * 31x10), c2 = c1@A2 + b2 ---------------
__global__ void collapse2(const float* __restrict__ W2, const float* __restrict__ b2) {
    int e = blockIdx.x * blockDim.x + threadIdx.x;
    if (e < D_IN * D_OUT) {
        int i = e % D_IN;
        int j = e / D_IN;
        float s = 0.f;
        #pragma unroll
        for (int k = 0; k < D2; ++k)
            s = fmaf(g_T1[i * D2 + k], W2[j * D2 + k], s);
        g_T2[i * D_OUT + j] = s;
    }
    if (e < D_OUT) {
        float s = 0.f;
        for (int k = 0; k < D2; ++k)
            s = fmaf(g_c1[k], W2[e * D2 + k], s);
        g_c2[e] = s + b2[e];
    }
}

// ---- Stage 3 (single block): fold layers 3..8 (all 10x10), then Mf, cf -----
__global__ void collapse3(const float* __restrict__ W3, const float* __restrict__ b3,
                          const float* __restrict__ W4, const float* __restrict__ b4,
                          const float* __restrict__ W5, const float* __restrict__ b5,
                          const float* __restrict__ W6, const float* __restrict__ b6,
                          const float* __restrict__ W7, const float* __restrict__ b7,
                          const float* __restrict__ W8, const float* __restrict__ b8) {
    __shared__ float R[2][100];   // R[k*10+j]
    __shared__ float r[2][10];
    int t = threadIdx.x;

    if (t < 100) R[0][t] = W3[(t % 10) * 10 + (t / 10)];   // R[k][j] = W3[j][k]
    if (t < 10)  r[0][t] = b3[t];
    __syncthreads();

    const float* Ws[5] = {W4, W5, W6, W7, W8};
    const float* bs[5] = {b4, b5, b6, b7, b8};
    int cur = 0;
    for (int l = 0; l < 5; ++l) {
        const float* W = Ws[l];
        const float* b = bs[l];
        int nxt = cur ^ 1;
        if (t < 100) {
            int k = t / 10, j = t % 10;
            float s = 0.f;
            #pragma unroll
            for (int m = 0; m < 10; ++m)
                s = fmaf(R[cur][k * 10 + m], W[j * 10 + m], s);
            R[nxt][t] = s;
        }
        if (t < 10) {
            float s = 0.f;
            #pragma unroll
            for (int m = 0; m < 10; ++m)
                s = fmaf(r[cur][m], W[t * 10 + m], s);
            r[nxt][t] = s + b[t];
        }
        __syncthreads();
        cur = nxt;
    }

    // Mf = T2 @ R, cf = c2 @ R + r
    for (int e = t; e < D_IN * D_OUT; e += blockDim.x) {
        int i = e / D_OUT, j = e % D_OUT;
        float s = 0.f;
        #pragma unroll
        for (int k = 0; k < 10; ++k)
            s = fmaf(g_T2[i * 10 + k], R[cur][k * 10 + j], s);
        g_Mf[e] = s;
    }
    if (t < D_OUT) {
        float s = 0.f;
        #pragma unroll
        for (int k = 0; k < 10; ++k)
            s = fmaf(g_c2[k], R[cur][k * 10 + t], s);
        g_cf[t] = s + r[cur][t];
    }
}

// ---- Main pass: out[65536,10] = x @ Mf + cf --------------------------------
// Warp owns 8 rows; lanes split k (stride 32) -> coalesced LDG.32 on x.
// Mf in shared, pitch 11 -> conflict-free lane-strided reads.
// Butterfly shuffle reduce, predicated epilogue stores.
__global__ __launch_bounds__(256, 2)
void mlp_fused(const float* __restrict__ x, float* __restrict__ out) {
    __shared__ float Msh[D_IN * M_PITCH];  // 8624 floats = 34.5 KB
    __shared__ float cfs[D_OUT];

    int t = threadIdx.x;
    for (int i = t; i < D_IN * D_OUT; i += 256) {
        int k = i / D_OUT, j = i % D_OUT;
        Msh[k * M_PITCH + j] = g_Mf[i];
    }
    if (t < D_OUT) cfs[t] = g_cf[t];
    __syncthreads();

    int warp = t >> 5;
    int lane = t & 31;
    int rowbase = (blockIdx.x * 8 + warp) * 8;     // 8 rows per warp
    const float* xp = x + (size_t)rowbase * D_IN + lane;

    float acc[8][10];
    #pragma unroll
    for (int rr = 0; rr < 8; ++rr)
        #pragma unroll
        for (int j = 0; j < 10; ++j) acc[rr][j] = 0.f;

    // 24 full k-iterations (k = kb + lane), kb = 0..736
    #pragma unroll 2
    for (int kb = 0; kb < 768; kb += 32) {
        float xv[8];
        #pragma unroll
        for (int rr = 0; rr < 8; ++rr)
            xv[rr] = xp[rr * D_IN + kb];           // coalesced: lane-stride 4B
        const float* mrow = &Msh[(kb + lane) * M_PITCH];
        float m[10];
        #pragma unroll
        for (int j = 0; j < 10; ++j) m[j] = mrow[j];
        #pragma unroll
        for (int rr = 0; rr < 8; ++rr)
            #pragma unroll
            for (int j = 0; j < 10; ++j)
                acc[rr][j] = fmaf(xv[rr], m[j], acc[rr][j]);
    }
    // tail: kb = 768, 16 valid lanes (784 = 24*32 + 16)
    if (lane < 16) {
        const float* mrow = &Msh[(768 + lane) * M_PITCH];
        float m[10];
        #pragma unroll
        for (int j = 0; j < 10; ++j) m[j] = mrow[j];
        #pragma unroll
        for (int rr = 0; rr < 8; ++rr) {
            float xv = xp[rr * D_IN + 768];
            #pragma unroll
            for (int j = 0; j < 10; ++j)
                acc[rr][j] = fmaf(xv, m[j], acc[rr][j]);
        }
    }

    // butterfly reduce across 32 lanes
    #pragma unroll
    for (int off = 16; off > 0; off >>= 1)
        #pragma unroll
        for (int rr = 0; rr < 8; ++rr)
            #pragma unroll
            for (int j = 0; j < 10; ++j)
                acc[rr][j] += __shfl_xor_sync(0xffffffffu, acc[rr][j], off);

    // epilogue: lane j writes column j (coalesced 40B burst per row)
    #pragma unroll
    for (int rr = 0; rr < 8; ++rr) {
        int orow = (rowbase + rr) * D_OUT;
        #pragma unroll
        for (int j = 0; j < 10; ++j)
            if (lane == j) out[orow + j] = acc[rr][j] + cfs[j];
    }
}

// ---------------------------------------------------------------------------
extern "C" void kernel_launch(void* const* d_in, const int* in_sizes, int n_in,
                              void* d_out, int out_size) {
    const float* x  = (const float*)d_in[0];
    const float* W0 = (const float*)d_in[1];
    const float* b0 = (const float*)d_in[2];
    const float* W1 = (const float*)d_in[3];
    const float* b1 = (const float*)d_in[4];
    const float* W2 = (const float*)d_in[5];
    const float* b2 = (const float*)d_in[6];
    const float* W3 = (const float*)d_in[7];
    const float* b3 = (const float*)d_in[8];
    const float* W4 = (const float*)d_in[9];
    const float* b4 = (const float*)d_in[10];
    const float* W5 = (const float*)d_in[11];
    const float* b5 = (const float*)d_in[12];
    const float* W6 = (const float*)d_in[13];
    const float* b6 = (const float*)d_in[14];
    const float* W7 = (const float*)d_in[15];
    const float* b7 = (const float*)d_in[16];
    const float* W8 = (const float*)d_in[17];
    const float* b8 = (const float*)d_in[18];
    float* out = (float*)d_out;

    collapse1<<<(D_IN * D2 + 255) / 256, 256>>>(W0, b0, W1, b1);
    collapse2<<<(D_IN * D_OUT + 255) / 256, 256>>>(W2, b2);
    collapse3<<<1, 256>>>(W3, b3, W4, b4, W5, b5, W6, b6, W7, b7, W8, b8);
    mlp_fused<<<BATCH / 64, 256>>>(x, out);   // 1024 blocks x 256 thr, 64 rows/block
}

// round 4
// speedup vs baseline: 1.4134x; 1.4134x over previous
#include <cuda_runtime.h>
#include <cuda_bf16.h>
#include <cstdint>

// ---------------------------------------------------------------------------
// OnlyLinear chain collapsed to y = x @ Mf + cf, then one HBM-bound pass using
// Blackwell fma.rn.f32x2 (packed dual-fp32 FMA) with (k-even,k-odd) pairing.
// ---------------------------------------------------------------------------

#define BSZ     65536
#define KDIM    784
#define NOUT    10

// main kernel tiling
#define TPB     224          // threads per block == rows per block (7 warps)
#define ROWS    224
#define CK      32           // k-chunk staged in smem
#define NCH     24           // full chunks (24*32=768), tail = 16
#define XPITCH  36           // x tile pitch: mult of 4, ==4 mod 32 -> conflict-free .128
#define MPITCH  800          // M SoA pitch (floats), 800*4 % 16 == 0

// __device__ scratch (allocation-free rule)
__device__ float g_S[69 * NOUT];          // A1@A2@P  (69 x 10)
__device__ float g_Mf[KDIM * NOUT];       // collapsed matrix (row-major [k][j])
__device__ float g_cf[NOUT];              // collapsed bias

// ---- packed f32x2 helpers --------------------------------------------------
__device__ __forceinline__ unsigned long long ffma2(unsigned long long a,
                                                    unsigned long long b,
                                                    unsigned long long c) {
    unsigned long long d;
    asm("fma.rn.f32x2 %0, %1, %2, %3;" : "=l"(d) : "l"(a), "l"(b), "l"(c));
    return d;
}
__device__ __forceinline__ float2 unpack2(unsigned long long v) {
    float2 r;
    asm("mov.b64 {%0, %1}, %2;" : "=f"(r.x), "=f"(r.y) : "l"(v));
    return r;
}

// ---------------------------------------------------------------------------
// collapse kernel 1 (single block, 128 thr): right-associated fold.
//   R = A3*A4*...*A8 (10x10), Q = A2@R (31x10), S = A1@Q (69x10) -> g_S
//   bias fold: c1 = b0@A1+b1; c2 = c1@A2+b2; then c <- c@Al + bl, l=3..8 -> g_cf
// ---------------------------------------------------------------------------
__global__ void collapse_small(const float* __restrict__ W1, const float* __restrict__ b1,
                               const float* __restrict__ W2, const float* __restrict__ b2,
                               const float* __restrict__ W3, const float* __restrict__ b3,
                               const float* __restrict__ W4, const float* __restrict__ b4,
                               const float* __restrict__ W5, const float* __restrict__ b5,
                               const float* __restrict__ W6, const float* __restrict__ b6,
                               const float* __restrict__ W7, const float* __restrict__ b7,
                               const float* __restrict__ W8, const float* __restrict__ b8,
                               const float* __restrict__ b0) {
    __shared__ float R[2][100];     // R[k*10+j]
    __shared__ float Q[31 * 10];
    __shared__ float c1s[31];
    __shared__ float cs[2][10];
    int t = threadIdx.x;

    // R init = A3 : R[k][j] = W3[j][k]
    if (t < 100) R[0][t] = W3[(t % 10) * 10 + (t / 10)];
    // c1 = b0@A1 + b1 (independent of R)
    if (t < 31) {
        float s = b1[t];
        for (int k = 0; k < 69; ++k) s = fmaf(b0[k], W1[t * 69 + k], s);
        c1s[t] = s;
    }
    __syncthreads();

    // fold A4..A8 into R
    const float* Wf[5] = {W4, W5, W6, W7, W8};
    int cur = 0;
    for (int l = 0; l < 5; ++l) {
        const float* W = Wf[l];
        int nxt = cur ^ 1;
        if (t < 100) {
            int k = t / 10, j = t % 10;
            float s = 0.f;
            #pragma unroll
            for (int m = 0; m < 10; ++m)
                s = fmaf(R[cur][k * 10 + m], W[j * 10 + m], s);
            R[nxt][t] = s;
        }
        __syncthreads();
        cur = nxt;
    }

    // Q[k][j] = sum_m W2[m*31+k] * R[m][j]   (31x10)
    for (int e = t; e < 310; e += blockDim.x) {
        int k = e / 10, j = e % 10;
        float s = 0.f;
        #pragma unroll
        for (int m = 0; m < 10; ++m)
            s = fmaf(W2[m * 31 + k], R[cur][m * 10 + j], s);
        Q[e] = s;
    }
    // c2 = c1@A2 + b2
    if (t < 10) {
        float s = b2[t];
        for (int m = 0; m < 31; ++m) s = fmaf(c1s[m], W2[t * 31 + m], s);
        cs[0][t] = s;
    }
    __syncthreads();

    // S[k][j] = sum_m W1[m*69+k] * Q[m][j]   (69x10) -> global
    for (int e = t; e < 690; e += blockDim.x) {
        int k = e / 10, j = e % 10;
        float s = 0.f;
        #pragma unroll 4
        for (int m = 0; m < 31; ++m)
            s = fmaf(W1[m * 69 + k], Q[m * 10 + j], s);
        g_S[e] = s;
    }

    // bias fold through layers 3..8
    const float* Wl[6] = {W3, W4, W5, W6, W7, W8};
    const float* bl[6] = {b3, b4, b5, b6, b7, b8};
    int cb = 0;
    for (int l = 0; l < 6; ++l) {
        int nb = cb ^ 1;
        if (t < 10) {
            float s = bl[l][t];
            #pragma unroll
            for (int m = 0; m < 10; ++m)
                s = fmaf(cs[cb][m], Wl[l][t * 10 + m], s);
            cs[nb][t] = s;
        }
        __syncthreads();
        cb = nb;
    }
    if (t < 10) g_cf[t] = cs[cb][t];
}

// ---------------------------------------------------------------------------
// collapse kernel 2: Mf[i][j] = sum_k W0[k*784+i] * S[k][j]   (784x10)
// ---------------------------------------------------------------------------
__global__ void collapse_mf(const float* __restrict__ W0) {
    int e = blockIdx.x * blockDim.x + threadIdx.x;
    if (e >= KDIM * NOUT) return;
    int j = e / KDIM;
    int i = e % KDIM;          // adjacent threads -> adjacent i -> coalesced W0
    float s = 0.f;
    #pragma unroll 3
    for (int k = 0; k < 69; ++k)
        s = fmaf(W0[k * KDIM + i], g_S[k * 10 + j], s);
    g_Mf[i * 10 + j] = s;
}

// ---------------------------------------------------------------------------
// main pass: thread-per-row, lockstep k-march.
//  - M in smem transposed SoA Msm[j][k] -> broadcast LDS.128, natural f32x2 pairs
//  - x staged through double-buffered smem tile (coalesced LDG.128, prefetch)
//  - accumulate with fma.rn.f32x2 over (k,k+1) pairs
// ---------------------------------------------------------------------------
__global__ __launch_bounds__(TPB, 2)
void mlp_main(const float* __restrict__ x, float* __restrict__ out) {
    extern __shared__ float sm[];
    float* Msm   = sm;                        // 10 * 800
    float* tileA = sm + NOUT * MPITCH;        // 224 * 36
    float* tileB = tileA + ROWS * XPITCH;     // 224 * 36
    __shared__ float cfs[NOUT];

    const int t = threadIdx.x;
    const int rowbase = blockIdx.x * ROWS;

    // load M transposed: Msm[j*800 + k] = g_Mf[k*10 + j]
    for (int i = t; i < KDIM * NOUT; i += TPB) {
        int k = i / 10, j = i % 10;
        Msm[j * MPITCH + k] = g_Mf[i];
    }
    if (t < NOUT) cfs[t] = g_cf[t];

    // prefetch chunk 0 into regs, store to tileA
    float4 v[8];
    #pragma unroll
    for (int q = 0; q < 8; ++q) {
        int f4i = q * TPB + t;
        int r = f4i >> 3, c = f4i & 7;
        int gr = rowbase + r;
        int kk = (c << 2);
        v[q] = (gr < BSZ) ? *(const float4*)(x + (size_t)gr * KDIM + kk)
                          : make_float4(0.f, 0.f, 0.f, 0.f);
    }
    #pragma unroll
    for (int q = 0; q < 8; ++q) {
        int f4i = q * TPB + t;
        int r = f4i >> 3, c = f4i & 7;
        *(float4*)(tileA + r * XPITCH + (c << 2)) = v[q];
    }
    __syncthreads();

    unsigned long long acc[NOUT];
    #pragma unroll
    for (int j = 0; j < NOUT; ++j) acc[j] = 0ULL;

    int buf = 0;
    #pragma unroll 1
    for (int ch = 0; ch < NCH; ++ch) {
        // prefetch chunk ch+1 (global -> regs); tail chunk is partially guarded
        const int kbn = (ch + 1) * CK;
        #pragma unroll
        for (int q = 0; q < 8; ++q) {
            int f4i = q * TPB + t;
            int r = f4i >> 3, c = f4i & 7;
            int gr = rowbase + r;
            int kk = kbn + (c << 2);
            bool ok = (gr < BSZ) && (kk < KDIM);
            v[q] = ok ? *(const float4*)(x + (size_t)gr * KDIM + kk)
                      : make_float4(0.f, 0.f, 0.f, 0.f);
        }
        // compute current chunk from tile[buf]
        {
            const float* tp = (buf ? tileB : tileA) + t * XPITCH;
            const int kb = ch * CK;
            #pragma unroll
            for (int kk = 0; kk < CK; kk += 4) {
                ulonglong2 xq = *(const ulonglong2*)(tp + kk);
                #pragma unroll
                for (int j = 0; j < NOUT; ++j) {
                    ulonglong2 mq = *(const ulonglong2*)(Msm + j * MPITCH + kb + kk);
                    acc[j] = ffma2(xq.x, mq.x, acc[j]);
                    acc[j] = ffma2(xq.y, mq.y, acc[j]);
                }
            }
        }
        // stage prefetched chunk into the other buffer
        {
            float* tw = buf ? tileA : tileB;
            #pragma unroll
            for (int q = 0; q < 8; ++q) {
                int f4i = q * TPB + t;
                int r = f4i >> 3, c = f4i & 7;
                *(float4*)(tw + r * XPITCH + (c << 2)) = v[q];
            }
        }
        __syncthreads();
        buf ^= 1;
    }

    // tail chunk: kb = 768, 16 valid k
    {
        const float* tp = (buf ? tileB : tileA) + t * XPITCH;
        #pragma unroll
        for (int kk = 0; kk < 16; kk += 4) {
            ulonglong2 xq = *(const ulonglong2*)(tp + kk);
            #pragma unroll
            for (int j = 0; j < NOUT; ++j) {
                ulonglong2 mq = *(const ulonglong2*)(Msm + j * MPITCH + 768 + kk);
                acc[j] = ffma2(xq.x, mq.x, acc[j]);
                acc[j] = ffma2(xq.y, mq.y, acc[j]);
            }
        }
    }

    // epilogue
    const int row = rowbase + t;
    if (row < BSZ) {
        float res[NOUT];
        #pragma unroll
        for (int j = 0; j < NOUT; ++j) {
            float2 p = unpack2(acc[j]);
            res[j] = p.x + p.y + cfs[j];
        }
        float* op = out + (size_t)row * NOUT;
        #pragma unroll
        for (int p2 = 0; p2 < 5; ++p2)
            *(float2*)(op + 2 * p2) = make_float2(res[2 * p2], res[2 * p2 + 1]);
    }
}

// ---------------------------------------------------------------------------
extern "C" void kernel_launch(void* const* d_in, const int* in_sizes, int n_in,
                              void* d_out, int out_size) {
    const float* x  = (const float*)d_in[0];
    const float* W0 = (const float*)d_in[1];
    const float* b0 = (const float*)d_in[2];
    const float* W1 = (const float*)d_in[3];
    const float* b1 = (const float*)d_in[4];
    const float* W2 = (const float*)d_in[5];
    const float* b2 = (const float*)d_in[6];
    const float* W3 = (const float*)d_in[7];
    const float* b3 = (const float*)d_in[8];
    const float* W4 = (const float*)d_in[9];
    const float* b4 = (const float*)d_in[10];
    const float* W5 = (const float*)d_in[11];
    const float* b5 = (const float*)d_in[12];
    const float* W6 = (const float*)d_in[13];
    const float* b6 = (const float*)d_in[14];
    const float* W7 = (const float*)d_in[15];
    const float* b7 = (const float*)d_in[16];
    const float* W8 = (const float*)d_in[17];
    const float* b8 = (const float*)d_in[18];
    float* out = (float*)d_out;

    static bool attr_set = false;
    const int smem_bytes = (NOUT * MPITCH + 2 * ROWS * XPITCH) * sizeof(float); // 96512
    if (!attr_set) {
        cudaFuncSetAttribute(mlp_main, cudaFuncAttributeMaxDynamicSharedMemorySize, smem_bytes);
        attr_set = true;
    }

    collapse_small<<<1, 128>>>(W1, b1, W2, b2, W3, b3, W4, b4,
                               W5, b5, W6, b6, W7, b7, W8, b8, b0);
    collapse_mf<<<(KDIM * NOUT + 255) / 256, 256>>>(W0);

    const int grid = (BSZ + ROWS - 1) / ROWS;   // 293
    mlp_main<<<grid, TPB, smem_bytes>>>(x, out);
}